// round 6
// baseline (speedup 1.0000x reference)
#include <cuda_runtime.h>
#include <cuda_bf16.h>
#include <cstdint>
#include <cstddef>

// ---------------------------------------------------------------------------
// Problem constants
// ---------------------------------------------------------------------------
#define BDIM   2
#define SDIM   2048
#define DDIM   2048
#define HEADS  16
#define KVH    4
#define HD     128
#define QR     6
#define RR     2
#define BS     (BDIM * SDIM)          // 4096 tokens
#define NPAD   1408                   // packed projection width (11*128)

// ---------------------------------------------------------------------------
// Scratch (device globals; no runtime allocation allowed)
// ---------------------------------------------------------------------------
__device__ __nv_bfloat16 g_Wc_hi[(size_t)NPAD * DDIM];   // Wcat^T [n][k]
__device__ __nv_bfloat16 g_Wc_lo[(size_t)NPAD * DDIM];
__device__ __nv_bfloat16 g_Wo_hi[(size_t)DDIM * DDIM];   // Wo^T [n][k]
__device__ __nv_bfloat16 g_Wo_lo[(size_t)DDIM * DDIM];
__device__ __nv_bfloat16 g_X_hi[(size_t)BS * DDIM];      // hidden_states
__device__ __nv_bfloat16 g_X_lo[(size_t)BS * DDIM];
__device__ __nv_bfloat16 g_A_hi[(size_t)BS * DDIM];      // attention output
__device__ __nv_bfloat16 g_A_lo[(size_t)BS * DDIM];
__device__ float g_proj[(size_t)BS * NPAD];              // X @ Wcat (fp32)
__device__ __nv_bfloat16 g_qhi[(size_t)BDIM * HEADS * SDIM * HD];
__device__ __nv_bfloat16 g_qlo[(size_t)BDIM * HEADS * SDIM * HD];
__device__ __nv_bfloat16 g_khi[(size_t)BDIM * KVH * SDIM * HD];
__device__ __nv_bfloat16 g_klo[(size_t)BDIM * KVH * SDIM * HD];
__device__ __nv_bfloat16 g_vhi[(size_t)BDIM * KVH * SDIM * HD];
__device__ __nv_bfloat16 g_vlo[(size_t)BDIM * KVH * SDIM * HD];

// ---------------------------------------------------------------------------
// PTX helpers (sm_80+ features only: mma.sync, ldmatrix, cp.async)
// ---------------------------------------------------------------------------
__device__ __forceinline__ uint32_t smem_to_u32(const void* p) {
    uint32_t a;
    asm("{ .reg .u64 t; cvta.to.shared.u64 t, %1; cvt.u32.u64 %0, t; }"
        : "=r"(a) : "l"(p));
    return a;
}
__device__ __forceinline__ void ldsm_x4(uint32_t* r, uint32_t addr) {
    asm volatile("ldmatrix.sync.aligned.m8n8.x4.shared.b16 {%0,%1,%2,%3}, [%4];"
        : "=r"(r[0]), "=r"(r[1]), "=r"(r[2]), "=r"(r[3]) : "r"(addr));
}
__device__ __forceinline__ void ldsm_x4_t(uint32_t* r, uint32_t addr) {
    asm volatile("ldmatrix.sync.aligned.m8n8.x4.trans.shared.b16 {%0,%1,%2,%3}, [%4];"
        : "=r"(r[0]), "=r"(r[1]), "=r"(r[2]), "=r"(r[3]) : "r"(addr));
}
__device__ __forceinline__ void mma16816(float* c, const uint32_t* a,
                                         uint32_t b0, uint32_t b1) {
    asm volatile(
        "mma.sync.aligned.m16n8k16.row.col.f32.bf16.bf16.f32 "
        "{%0,%1,%2,%3}, {%4,%5,%6,%7}, {%8,%9}, {%0,%1,%2,%3};"
        : "+f"(c[0]), "+f"(c[1]), "+f"(c[2]), "+f"(c[3])
        : "r"(a[0]), "r"(a[1]), "r"(a[2]), "r"(a[3]), "r"(b0), "r"(b1));
}
__device__ __forceinline__ void cp16(uint32_t dst, const void* src) {
    asm volatile("cp.async.cg.shared.global [%0], [%1], 16;" :: "r"(dst), "l"(src));
}
#define CP_COMMIT() asm volatile("cp.async.commit_group;")
#define CP_WAIT0()  asm volatile("cp.async.wait_group 0;")
#define CP_WAIT1()  asm volatile("cp.async.wait_group 1;")

// pack two floats to bf16x2 (lo -> low half, hi -> high half)
__device__ __forceinline__ uint32_t pack_bf16x2(float lo, float hi) {
    uint32_t d;
    asm("cvt.rn.bf16x2.f32 %0, %1, %2;" : "=r"(d) : "f"(hi), "f"(lo));
    return d;
}
// split a float pair into hi/lo bf16x2 words
__device__ __forceinline__ void split2(float x0, float x1,
                                       uint32_t& hi, uint32_t& lo) {
    hi = pack_bf16x2(x0, x1);
    float h0 = __uint_as_float(hi << 16);
    float h1 = __uint_as_float(hi & 0xffff0000u);
    lo = pack_bf16x2(x0 - h0, x1 - h1);
}

// ---------------------------------------------------------------------------
// Kernel 1a: pack six projection weights transposed into bf16 hi/lo [n][k]
// ---------------------------------------------------------------------------
__global__ void pack_w_kernel(const float* __restrict__ waq,
                              const float* __restrict__ wak,
                              const float* __restrict__ wav,
                              const float* __restrict__ wbq,
                              const float* __restrict__ wbk,
                              const float* __restrict__ wbv) {
    size_t idx = (size_t)blockIdx.x * blockDim.x + threadIdx.x;
    if (idx >= (size_t)NPAD * DDIM) return;
    int n = (int)(idx / DDIM);
    int k = (int)(idx % DDIM);
    float val = 0.0f;
    if (n < 96)        val = waq[(size_t)k * 96  + n];
    else if (n < 104)  val = wak[(size_t)k * 8   + (n - 96)];
    else if (n < 112)  val = wav[(size_t)k * 8   + (n - 104)];
    else if (n < 880)  val = wbq[(size_t)k * 768 + (n - 112)];
    else if (n < 1136) val = wbk[(size_t)k * 256 + (n - 880)];
    else if (n < 1392) val = wbv[(size_t)k * 256 + (n - 1136)];
    __nv_bfloat16 h = __float2bfloat16(val);
    g_Wc_hi[idx] = h;
    g_Wc_lo[idx] = __float2bfloat16(val - __bfloat162float(h));
}

__global__ void pack_wo_kernel(const float* __restrict__ wo) {
    size_t idx = (size_t)blockIdx.x * blockDim.x + threadIdx.x;
    if (idx >= (size_t)DDIM * DDIM) return;
    int n = (int)(idx / DDIM);
    int k = (int)(idx % DDIM);
    float val = wo[(size_t)k * DDIM + n];
    __nv_bfloat16 h = __float2bfloat16(val);
    g_Wo_hi[idx] = h;
    g_Wo_lo[idx] = __float2bfloat16(val - __bfloat162float(h));
}

__global__ void split_x_kernel(const float* __restrict__ x) {
    size_t idx = (size_t)blockIdx.x * blockDim.x + threadIdx.x;
    if (idx >= (size_t)BS * DDIM) return;
    float v = x[idx];
    __nv_bfloat16 h = __float2bfloat16(v);
    g_X_hi[idx] = h;
    g_X_lo[idx] = __float2bfloat16(v - __bfloat162float(h));
}

// ---------------------------------------------------------------------------
// HMMA split-bf16 GEMM v2: C[M,N] = (Ah+Al)[M,K] @ (Bh+Bl)^T, B stored [N][K].
// Block tile 256x128, 8 warps as 4m x 2n, warp tile 64x64 (halved smem
// traffic per FLOP vs 64x32). k-chunk 32, cp.async double buffer.
// SMEM rows padded to 80B (conflict-free ldmatrix).
// ---------------------------------------------------------------------------
#define GRS    80                      // smem row stride bytes (64 data + 16)
#define APLANE (256 * GRS)             // 20480 B (A has 256 rows)
#define BPLANE (128 * GRS)             // 10240 B (B has 128 rows)
#define GBUF   (2 * APLANE + 2 * BPLANE)   // 61440 B per buffer
#define GEMM_SMEM (2 * GBUF)           // 122880 B

__device__ __forceinline__
void hgemm_body(const __nv_bfloat16* __restrict__ Ah,
                const __nv_bfloat16* __restrict__ Al,
                const __nv_bfloat16* __restrict__ Bh,
                const __nv_bfloat16* __restrict__ Bl,
                float* __restrict__ C, int N, int K) {
    extern __shared__ char gsm[];
    const uint32_t sb = smem_to_u32(gsm);
    const int tid = threadIdx.x, lane = tid & 31;
    const int wid = tid >> 5;
    const int wm = wid >> 1, wn = wid & 1;       // 4m x 2n, warp tile 64x64
    const int bm = blockIdx.y * 256, bn = blockIdx.x * 128;

    float acc[4][8][4];
#pragma unroll
    for (int i = 0; i < 4; i++)
#pragma unroll
        for (int j = 0; j < 8; j++)
#pragma unroll
            for (int e = 0; e < 4; e++) acc[i][j][e] = 0.0f;

    // 3072 cp16 per chunk: Ah 1024, Al 1024, Bh 512, Bl 512
    auto issue = [&](int k0, int buf) {
#pragma unroll
        for (int i = 0; i < 12; i++) {
            int idx = tid + i * 256;
            const __nv_bfloat16* g;
            int rb, r; uint32_t off;
            if (idx < 1024)      { g = Ah; rb = bm; r = idx >> 2;          off = 0; }
            else if (idx < 2048) { g = Al; rb = bm; r = (idx - 1024) >> 2; off = APLANE; }
            else if (idx < 2560) { g = Bh; rb = bn; r = (idx - 2048) >> 2; off = 2 * APLANE; }
            else                 { g = Bl; rb = bn; r = (idx - 2560) >> 2; off = 2 * APLANE + BPLANE; }
            int q = idx & 3;
            uint32_t dst = sb + buf * GBUF + off + r * GRS + q * 16;
            cp16(dst, g + (size_t)(rb + r) * K + k0 + q * 8);
        }
        CP_COMMIT();
    };

    const int nch = K / 32;
    issue(0, 0);
    for (int j = 0; j < nch; j++) {
        if (j + 1 < nch) { issue((j + 1) * 32, (j + 1) & 1); CP_WAIT1(); }
        else             { CP_WAIT0(); }
        __syncthreads();
        const uint32_t base = sb + (j & 1) * GBUF;
#pragma unroll
        for (int ks = 0; ks < 2; ks++) {
            uint32_t ah[4][4], al[4][4];
#pragma unroll
            for (int mt = 0; mt < 4; mt++) {
                uint32_t a = base + (wm * 64 + mt * 16 + (lane & 15)) * GRS
                           + ks * 32 + (lane >> 4) * 16;
                ldsm_x4(ah[mt], a);
                ldsm_x4(al[mt], a + APLANE);
            }
            uint32_t bh[8][2], bl[8][2];
#pragma unroll
            for (int p = 0; p < 4; p++) {
                uint32_t r4[4], r4l[4];
                uint32_t a = base + 2 * APLANE
                           + (wn * 64 + p * 16 + (lane & 15)) * GRS
                           + ks * 32 + (lane >> 4) * 16;
                ldsm_x4(r4, a);
                ldsm_x4(r4l, a + BPLANE);
                bh[2*p][0] = r4[0];  bh[2*p][1] = r4[2];
                bh[2*p+1][0] = r4[1]; bh[2*p+1][1] = r4[3];
                bl[2*p][0] = r4l[0]; bl[2*p][1] = r4l[2];
                bl[2*p+1][0] = r4l[1]; bl[2*p+1][1] = r4l[3];
            }
#pragma unroll
            for (int mt = 0; mt < 4; mt++)
#pragma unroll
                for (int nt = 0; nt < 8; nt++) {
                    mma16816(acc[mt][nt], ah[mt], bh[nt][0], bh[nt][1]);
                    mma16816(acc[mt][nt], al[mt], bh[nt][0], bh[nt][1]);
                    mma16816(acc[mt][nt], ah[mt], bl[nt][0], bl[nt][1]);
                }
        }
        __syncthreads();
    }

#pragma unroll
    for (int mt = 0; mt < 4; mt++)
#pragma unroll
        for (int nt = 0; nt < 8; nt++) {
            int row = bm + wm * 64 + mt * 16 + (lane >> 2);
            int col = bn + wn * 64 + nt * 8 + ((lane & 3) << 1);
            *(float2*)(C + (size_t)row * N + col) =
                make_float2(acc[mt][nt][0], acc[mt][nt][1]);
            *(float2*)(C + (size_t)(row + 8) * N + col) =
                make_float2(acc[mt][nt][2], acc[mt][nt][3]);
        }
}

__global__ __launch_bounds__(256, 1)
void gemm_proj_hmma() {
    hgemm_body(g_X_hi, g_X_lo, g_Wc_hi, g_Wc_lo, g_proj, NPAD, DDIM);
}
__global__ __launch_bounds__(256, 1)
void gemm_out_hmma(float* __restrict__ out) {
    hgemm_body(g_A_hi, g_A_lo, g_Wo_hi, g_Wo_lo, out, DDIM, DDIM);
}

// ---------------------------------------------------------------------------
// Kernel 3: per-token RoPE + rank contraction; emits q,k,v as bf16 hi/lo
// ---------------------------------------------------------------------------
__global__ __launch_bounds__(128)
void qkv_kernel(const float* __restrict__ cosg, const float* __restrict__ sing) {
    const int t = blockIdx.x;
    const int b = t >> 11;
    const int s = t & 2047;
    const float* __restrict__ row = &g_proj[(size_t)t * NPAD];

    __shared__ float aq[96];
    __shared__ float akv[16];
    __shared__ float bq[QR][HD];
    __shared__ float bk[RR][HD];
    __shared__ float bv[RR][HD];
    __shared__ float cs[64], sn[64];

    const int tid = threadIdx.x;
    if (tid < 64) { cs[tid] = cosg[(size_t)t * 64 + tid]; sn[tid] = sing[(size_t)t * 64 + tid]; }
    if (tid < 96) aq[tid] = row[tid];
    if (tid >= 96 && tid < 112) akv[tid - 96] = row[tid];
    __syncthreads();

    for (int p = tid; p < QR * 64; p += 128) {
        int r = p >> 6, d = p & 63;
        float x1 = row[112 + r * HD + d];
        float x2 = row[112 + r * HD + 64 + d];
        bq[r][d]      = x1 * cs[d] - x2 * sn[d];
        bq[r][64 + d] = x2 * cs[d] + x1 * sn[d];
    }
    {
        int r = tid >> 6, d = tid & 63;
        float x1 = row[880 + r * HD + d];
        float x2 = row[880 + r * HD + 64 + d];
        bk[r][d]      = x1 * cs[d] - x2 * sn[d];
        bk[r][64 + d] = x2 * cs[d] + x1 * sn[d];
    }
    for (int p = tid; p < RR * HD; p += 128) {
        bv[p >> 7][p & 127] = row[1136 + p];
    }
    __syncthreads();

    for (int idx = tid; idx < HEADS * HD; idx += 128) {
        int h = idx >> 7, d = idx & 127;
        float acc = 0.0f;
#pragma unroll
        for (int r = 0; r < QR; r++) acc += aq[h * QR + r] * bq[r][d];
        acc *= (1.0f / QR);
        size_t o = (((size_t)b * HEADS + h) * SDIM + s) * HD + d;
        __nv_bfloat16 hh = __float2bfloat16(acc);
        g_qhi[o] = hh;
        g_qlo[o] = __float2bfloat16(acc - __bfloat162float(hh));
    }
    for (int idx = tid; idx < KVH * HD; idx += 128) {
        int kh = idx >> 7, d = idx & 127;
        float ak0 = akv[kh * RR + 0], ak1 = akv[kh * RR + 1];
        float av0 = akv[8 + kh * RR + 0], av1 = akv[8 + kh * RR + 1];
        size_t o = (((size_t)b * KVH + kh) * SDIM + s) * HD + d;
        float kv = (ak0 * bk[0][d] + ak1 * bk[1][d]) * 0.5f;
        float vv = (av0 * bv[0][d] + av1 * bv[1][d]) * 0.5f;
        __nv_bfloat16 kh16 = __float2bfloat16(kv);
        g_khi[o] = kh16;
        g_klo[o] = __float2bfloat16(kv - __bfloat162float(kh16));
        __nv_bfloat16 vh16 = __float2bfloat16(vv);
        g_vhi[o] = vh16;
        g_vlo[o] = __float2bfloat16(vv - __bfloat162float(vh16));
    }
}

// ---------------------------------------------------------------------------
// Kernel 4: HMMA causal flash attention with logsumexp sink gate.
// Block: 128 q-rows x one (b,h); 8 warps, warp owns 16 q-rows.
// KT=64 key tiles. K/V hi/lo double-buffered via cp.async.
// ---------------------------------------------------------------------------
#define FRS 272                         // smem row stride bytes (256 + 16)
#define FQ_OFF  0                       // Q hi (128 rows)
#define FQL_OFF 34816                   // Q lo
#define KV0_OFF 69632                   // KV buffers start
#define KVPLANE 17408                   // 64 rows * 272
#define KVBUF   (4 * KVPLANE)           // Khi,Klo,Vhi,Vlo = 69632
#define FLASH_SMEM (KV0_OFF + 2 * KVBUF)   // 208896

__global__ __launch_bounds__(256, 1)
void flash_hmma(const float* __restrict__ sinks) {
    extern __shared__ char fsm[];
    const uint32_t sb = smem_to_u32(fsm);
    const int tid = threadIdx.x, lane = tid & 31, wid = tid >> 5;
    const int qt = blockIdx.x, h = blockIdx.y, b = blockIdx.z;
    const int qbase = qt * 128;
    const int wrow = wid * 16;

    const size_t kvbase = ((size_t)(b * KVH + (h >> 2))) * SDIM * HD;

    // prefetch lambda: K/V hi/lo tile jj into buffer buf
    auto kv_issue = [&](int jj, int buf) {
        const __nv_bfloat16* kh = g_khi + kvbase + (size_t)jj * 64 * HD;
        const __nv_bfloat16* kl = g_klo + kvbase + (size_t)jj * 64 * HD;
        const __nv_bfloat16* vh = g_vhi + kvbase + (size_t)jj * 64 * HD;
        const __nv_bfloat16* vl = g_vlo + kvbase + (size_t)jj * 64 * HD;
        const uint32_t kb = sb + KV0_OFF + buf * KVBUF;
        for (int u = tid; u < 1024; u += 256) {
            int r = u >> 4, c = u & 15;
            uint32_t o = r * FRS + c * 16;
            size_t gi = (size_t)r * HD + c * 8;
            cp16(kb + o,               kh + gi);
            cp16(kb + KVPLANE + o,     kl + gi);
            cp16(kb + 2 * KVPLANE + o, vh + gi);
            cp16(kb + 3 * KVPLANE + o, vl + gi);
        }
        CP_COMMIT();
    };

    // load Q tile (hi/lo planes) with plain loads
    {
        const __nv_bfloat16* qh = g_qhi + (((size_t)(b * HEADS + h)) * SDIM + qbase) * HD;
        const __nv_bfloat16* ql = g_qlo + (((size_t)(b * HEADS + h)) * SDIM + qbase) * HD;
        for (int u = tid; u < 2048; u += 256) {
            int r = u >> 4, c = u & 15;
            *(uint4*)(fsm + FQ_OFF  + r * FRS + c * 16) = *(const uint4*)(qh + r * HD + c * 8);
            *(uint4*)(fsm + FQL_OFF + r * FRS + c * 16) = *(const uint4*)(ql + r * HD + c * 8);
        }
    }

    float m0 = -1e30f, m1 = -1e30f, l0 = 0.0f, l1 = 0.0f;
    float acc[16][4];
#pragma unroll
    for (int i = 0; i < 16; i++)
#pragma unroll
        for (int e = 0; e < 4; e++) acc[i][e] = 0.0f;

    const int nkt = 2 * qt + 2;
    const float SC = 0.08838834764831843f;   // HD^-0.5

    kv_issue(0, 0);
    for (int j = 0; j < nkt; j++) {
        if (j + 1 < nkt) { kv_issue(j + 1, (j + 1) & 1); CP_WAIT1(); }
        else             { CP_WAIT0(); }
        __syncthreads();
        const uint32_t kvb = sb + KV0_OFF + (j & 1) * KVBUF;

        // ---- S = Q K^T (3-pass split bf16) ----
        float s[8][4];
#pragma unroll
        for (int nt = 0; nt < 8; nt++)
#pragma unroll
            for (int e = 0; e < 4; e++) s[nt][e] = 0.0f;

#pragma unroll
        for (int ks = 0; ks < 8; ks++) {
            uint32_t ah[4], alo[4];
            uint32_t aaddr = sb + FQ_OFF + (wrow + (lane & 15)) * FRS
                           + ks * 32 + (lane >> 4) * 16;
            ldsm_x4(ah, aaddr);
            ldsm_x4(alo, aaddr + (FQL_OFF - FQ_OFF));
#pragma unroll
            for (int p = 0; p < 4; p++) {
                uint32_t kb4[4], klr[4];
                uint32_t baddr = kvb + (p * 16 + (lane & 15)) * FRS
                               + ks * 32 + (lane >> 4) * 16;
                ldsm_x4(kb4, baddr);
                ldsm_x4(klr, baddr + KVPLANE);
                mma16816(s[2*p],   ah,  kb4[0], kb4[2]);
                mma16816(s[2*p],   alo, kb4[0], kb4[2]);
                mma16816(s[2*p],   ah,  klr[0], klr[2]);
                mma16816(s[2*p+1], ah,  kb4[1], kb4[3]);
                mma16816(s[2*p+1], alo, kb4[1], kb4[3]);
                mma16816(s[2*p+1], ah,  klr[1], klr[3]);
            }
        }

        // ---- scale + causal mask ----
        const int r0 = qbase + wrow + (lane >> 2);
        const bool tail = (j >= 2 * qt);
#pragma unroll
        for (int nt = 0; nt < 8; nt++) {
            int kc = j * 64 + nt * 8 + ((lane & 3) << 1);
            s[nt][0] *= SC; s[nt][1] *= SC; s[nt][2] *= SC; s[nt][3] *= SC;
            if (tail) {
                if (kc     > r0)     s[nt][0] = -1e30f;
                if (kc + 1 > r0)     s[nt][1] = -1e30f;
                if (kc     > r0 + 8) s[nt][2] = -1e30f;
                if (kc + 1 > r0 + 8) s[nt][3] = -1e30f;
            }
        }

        // ---- online softmax (rows r0, r0+8), quad reductions ----
        float mx0 = -1e30f, mx1 = -1e30f;
#pragma unroll
        for (int nt = 0; nt < 8; nt++) {
            mx0 = fmaxf(mx0, fmaxf(s[nt][0], s[nt][1]));
            mx1 = fmaxf(mx1, fmaxf(s[nt][2], s[nt][3]));
        }
        mx0 = fmaxf(mx0, __shfl_xor_sync(0xffffffffu, mx0, 1));
        mx0 = fmaxf(mx0, __shfl_xor_sync(0xffffffffu, mx0, 2));
        mx1 = fmaxf(mx1, __shfl_xor_sync(0xffffffffu, mx1, 1));
        mx1 = fmaxf(mx1, __shfl_xor_sync(0xffffffffu, mx1, 2));
        float mn0 = fmaxf(m0, mx0), mn1 = fmaxf(m1, mx1);
        float a0 = __expf(m0 - mn0), a1 = __expf(m1 - mn1);
        float sum0 = 0.0f, sum1 = 0.0f;
#pragma unroll
        for (int nt = 0; nt < 8; nt++) {
            s[nt][0] = __expf(s[nt][0] - mn0); sum0 += s[nt][0];
            s[nt][1] = __expf(s[nt][1] - mn0); sum0 += s[nt][1];
            s[nt][2] = __expf(s[nt][2] - mn1); sum1 += s[nt][2];
            s[nt][3] = __expf(s[nt][3] - mn1); sum1 += s[nt][3];
        }
        sum0 += __shfl_xor_sync(0xffffffffu, sum0, 1);
        sum0 += __shfl_xor_sync(0xffffffffu, sum0, 2);
        sum1 += __shfl_xor_sync(0xffffffffu, sum1, 1);
        sum1 += __shfl_xor_sync(0xffffffffu, sum1, 2);
        l0 = l0 * a0 + sum0; l1 = l1 * a1 + sum1;
        m0 = mn0; m1 = mn1;
#pragma unroll
        for (int dt = 0; dt < 16; dt++) {
            acc[dt][0] *= a0; acc[dt][1] *= a0;
            acc[dt][2] *= a1; acc[dt][3] *= a1;
        }

        // ---- PV: P split to bf16 hi/lo, V from SMEM via ldmatrix.trans ----
#pragma unroll
        for (int kt = 0; kt < 4; kt++) {
            uint32_t ph[4], pl[4];
            split2(s[2*kt][0],   s[2*kt][1],   ph[0], pl[0]);
            split2(s[2*kt][2],   s[2*kt][3],   ph[1], pl[1]);
            split2(s[2*kt+1][0], s[2*kt+1][1], ph[2], pl[2]);
            split2(s[2*kt+1][2], s[2*kt+1][3], ph[3], pl[3]);
#pragma unroll
            for (int dp = 0; dp < 8; dp++) {
                uint32_t vh[4], vl[4];
                uint32_t vaddr = kvb + 2 * KVPLANE + (kt * 16 + (lane & 15)) * FRS
                               + dp * 32 + (lane >> 4) * 16;
                ldsm_x4_t(vh, vaddr);
                ldsm_x4_t(vl, vaddr + KVPLANE);
                mma16816(acc[2*dp],   ph, vh[0], vh[1]);
                mma16816(acc[2*dp],   pl, vh[0], vh[1]);
                mma16816(acc[2*dp],   ph, vl[0], vl[1]);
                mma16816(acc[2*dp+1], ph, vh[2], vh[3]);
                mma16816(acc[2*dp+1], pl, vh[2], vh[3]);
                mma16816(acc[2*dp+1], ph, vl[2], vl[3]);
            }
        }
        __syncthreads();   // all warps done with this buffer before reuse
    }

    // ---- epilogue: sink gate, normalize, write bf16 hi/lo attention out ----
    const float sink = sinks[h];
    float logz0 = m0 + logf(l0);
    float logz1 = m1 + logf(l1);
    float sc0 = (1.0f / (1.0f + __expf(sink - logz0))) / l0;
    float sc1 = (1.0f / (1.0f + __expf(sink - logz1))) / l1;
    const int tok0 = b * SDIM + qbase + wrow + (lane >> 2);
    const int tok1 = tok0 + 8;
#pragma unroll
    for (int dt = 0; dt < 16; dt++) {
        int col = h * HD + dt * 8 + ((lane & 3) << 1);
        uint32_t hi, lo;
        split2(acc[dt][0] * sc0, acc[dt][1] * sc0, hi, lo);
        *(uint32_t*)(g_A_hi + (size_t)tok0 * DDIM + col) = hi;
        *(uint32_t*)(g_A_lo + (size_t)tok0 * DDIM + col) = lo;
        split2(acc[dt][2] * sc1, acc[dt][3] * sc1, hi, lo);
        *(uint32_t*)(g_A_hi + (size_t)tok1 * DDIM + col) = hi;
        *(uint32_t*)(g_A_lo + (size_t)tok1 * DDIM + col) = lo;
    }
}

// ---------------------------------------------------------------------------
// launch
// ---------------------------------------------------------------------------
extern "C" void kernel_launch(void* const* d_in, const int* in_sizes, int n_in,
                              void* d_out, int out_size) {
    const float* hs    = (const float*)d_in[0];
    const float* cosg  = (const float*)d_in[1];
    const float* sing  = (const float*)d_in[2];
    // d_in[3] = attention_mask (pure causal; reproduced analytically)
    const float* waq   = (const float*)d_in[4];
    const float* wak   = (const float*)d_in[5];
    const float* wav   = (const float*)d_in[6];
    const float* wbq   = (const float*)d_in[7];
    const float* wbk   = (const float*)d_in[8];
    const float* wbv   = (const float*)d_in[9];
    const float* wo    = (const float*)d_in[10];
    const float* sinks = (const float*)d_in[11];
    float* out = (float*)d_out;

    cudaFuncSetAttribute(gemm_proj_hmma,
                         cudaFuncAttributeMaxDynamicSharedMemorySize, GEMM_SMEM);
    cudaFuncSetAttribute(gemm_out_hmma,
                         cudaFuncAttributeMaxDynamicSharedMemorySize, GEMM_SMEM);
    cudaFuncSetAttribute(flash_hmma,
                         cudaFuncAttributeMaxDynamicSharedMemorySize, FLASH_SMEM);

    // 1. pack + split weights and activations
    {
        size_t n = (size_t)NPAD * DDIM;
        pack_w_kernel<<<(unsigned)((n + 255) / 256), 256>>>(waq, wak, wav, wbq, wbk, wbv);
    }
    {
        size_t n = (size_t)DDIM * DDIM;
        pack_wo_kernel<<<(unsigned)((n + 255) / 256), 256>>>(wo);
    }
    {
        size_t n = (size_t)BS * DDIM;
        split_x_kernel<<<(unsigned)((n + 255) / 256), 256>>>(hs);
    }
    // 2. fused projection GEMM (HMMA): (4096 x 2048) @ (2048 x 1408)
    gemm_proj_hmma<<<dim3(NPAD / 128, BS / 256), 256, GEMM_SMEM>>>();
    // 3. rope + q/k/v assembly (emits bf16 hi/lo)
    qkv_kernel<<<BS, 128>>>(cosg, sing);
    // 4. HMMA flash attention with sink gate (K/V double-buffered)
    flash_hmma<<<dim3(SDIM / 128, HEADS, BDIM), 256, FLASH_SMEM>>>(sinks);
    // 5. output GEMM (HMMA): (4096 x 2048) @ (2048 x 2048) -> d_out
    gemm_out_hmma<<<dim3(DDIM / 128, BS / 256), 256, GEMM_SMEM>>>(out);
}

// round 7
// speedup vs baseline: 1.0967x; 1.0967x over previous
#include <cuda_runtime.h>
#include <cuda_bf16.h>
#include <cstdint>
#include <cstddef>

// ---------------------------------------------------------------------------
// Problem constants
// ---------------------------------------------------------------------------
#define BDIM   2
#define SDIM   2048
#define DDIM   2048
#define HEADS  16
#define KVH    4
#define HD     128
#define QR     6
#define RR     2
#define BS     (BDIM * SDIM)          // 4096 tokens
#define NPAD   1408                   // packed projection width (11*128)

// ---------------------------------------------------------------------------
// Scratch (device globals; no runtime allocation allowed)
// ---------------------------------------------------------------------------
__device__ __nv_bfloat16 g_Wc_hi[(size_t)NPAD * DDIM];   // Wcat^T [n][k]
__device__ __nv_bfloat16 g_Wc_lo[(size_t)NPAD * DDIM];
__device__ __nv_bfloat16 g_Wo_hi[(size_t)DDIM * DDIM];   // Wo^T [n][k]
__device__ __nv_bfloat16 g_Wo_lo[(size_t)DDIM * DDIM];
__device__ __nv_bfloat16 g_X_hi[(size_t)BS * DDIM];      // hidden_states
__device__ __nv_bfloat16 g_X_lo[(size_t)BS * DDIM];
__device__ __nv_bfloat16 g_A_hi[(size_t)BS * DDIM];      // attention output
__device__ __nv_bfloat16 g_A_lo[(size_t)BS * DDIM];
__device__ float g_proj[(size_t)BS * NPAD];              // X @ Wcat (fp32)
__device__ __nv_bfloat16 g_qhi[(size_t)BDIM * HEADS * SDIM * HD];
__device__ __nv_bfloat16 g_qlo[(size_t)BDIM * HEADS * SDIM * HD];
__device__ __nv_bfloat16 g_khi[(size_t)BDIM * KVH * SDIM * HD];
__device__ __nv_bfloat16 g_klo[(size_t)BDIM * KVH * SDIM * HD];
__device__ __nv_bfloat16 g_vhi[(size_t)BDIM * KVH * SDIM * HD];
__device__ __nv_bfloat16 g_vlo[(size_t)BDIM * KVH * SDIM * HD];

// ---------------------------------------------------------------------------
// PTX helpers (sm_80+ features only: mma.sync, ldmatrix, cp.async)
// ---------------------------------------------------------------------------
__device__ __forceinline__ uint32_t smem_to_u32(const void* p) {
    uint32_t a;
    asm("{ .reg .u64 t; cvta.to.shared.u64 t, %1; cvt.u32.u64 %0, t; }"
        : "=r"(a) : "l"(p));
    return a;
}
__device__ __forceinline__ void ldsm_x4(uint32_t* r, uint32_t addr) {
    asm volatile("ldmatrix.sync.aligned.m8n8.x4.shared.b16 {%0,%1,%2,%3}, [%4];"
        : "=r"(r[0]), "=r"(r[1]), "=r"(r[2]), "=r"(r[3]) : "r"(addr));
}
__device__ __forceinline__ void ldsm_x4_t(uint32_t* r, uint32_t addr) {
    asm volatile("ldmatrix.sync.aligned.m8n8.x4.trans.shared.b16 {%0,%1,%2,%3}, [%4];"
        : "=r"(r[0]), "=r"(r[1]), "=r"(r[2]), "=r"(r[3]) : "r"(addr));
}
__device__ __forceinline__ void mma16816(float* c, const uint32_t* a,
                                         uint32_t b0, uint32_t b1) {
    asm volatile(
        "mma.sync.aligned.m16n8k16.row.col.f32.bf16.bf16.f32 "
        "{%0,%1,%2,%3}, {%4,%5,%6,%7}, {%8,%9}, {%0,%1,%2,%3};"
        : "+f"(c[0]), "+f"(c[1]), "+f"(c[2]), "+f"(c[3])
        : "r"(a[0]), "r"(a[1]), "r"(a[2]), "r"(a[3]), "r"(b0), "r"(b1));
}
__device__ __forceinline__ void cp16(uint32_t dst, const void* src) {
    asm volatile("cp.async.cg.shared.global [%0], [%1], 16;" :: "r"(dst), "l"(src));
}
#define CP_COMMIT() asm volatile("cp.async.commit_group;")
#define CP_WAIT0()  asm volatile("cp.async.wait_group 0;")
#define CP_WAIT1()  asm volatile("cp.async.wait_group 1;")

// pack two floats to bf16x2 (lo -> low half, hi -> high half)
__device__ __forceinline__ uint32_t pack_bf16x2(float lo, float hi) {
    uint32_t d;
    asm("cvt.rn.bf16x2.f32 %0, %1, %2;" : "=r"(d) : "f"(hi), "f"(lo));
    return d;
}
// split a float pair into hi/lo bf16x2 words
__device__ __forceinline__ void split2(float x0, float x1,
                                       uint32_t& hi, uint32_t& lo) {
    hi = pack_bf16x2(x0, x1);
    float h0 = __uint_as_float(hi << 16);
    float h1 = __uint_as_float(hi & 0xffff0000u);
    lo = pack_bf16x2(x0 - h0, x1 - h1);
}

// ---------------------------------------------------------------------------
// Kernel 1a: pack six projection weights transposed into bf16 hi/lo [n][k]
// ---------------------------------------------------------------------------
__global__ void pack_w_kernel(const float* __restrict__ waq,
                              const float* __restrict__ wak,
                              const float* __restrict__ wav,
                              const float* __restrict__ wbq,
                              const float* __restrict__ wbk,
                              const float* __restrict__ wbv) {
    size_t idx = (size_t)blockIdx.x * blockDim.x + threadIdx.x;
    if (idx >= (size_t)NPAD * DDIM) return;
    int n = (int)(idx / DDIM);
    int k = (int)(idx % DDIM);
    float val = 0.0f;
    if (n < 96)        val = waq[(size_t)k * 96  + n];
    else if (n < 104)  val = wak[(size_t)k * 8   + (n - 96)];
    else if (n < 112)  val = wav[(size_t)k * 8   + (n - 104)];
    else if (n < 880)  val = wbq[(size_t)k * 768 + (n - 112)];
    else if (n < 1136) val = wbk[(size_t)k * 256 + (n - 880)];
    else if (n < 1392) val = wbv[(size_t)k * 256 + (n - 1136)];
    __nv_bfloat16 h = __float2bfloat16(val);
    g_Wc_hi[idx] = h;
    g_Wc_lo[idx] = __float2bfloat16(val - __bfloat162float(h));
}

__global__ void pack_wo_kernel(const float* __restrict__ wo) {
    size_t idx = (size_t)blockIdx.x * blockDim.x + threadIdx.x;
    if (idx >= (size_t)DDIM * DDIM) return;
    int n = (int)(idx / DDIM);
    int k = (int)(idx % DDIM);
    float val = wo[(size_t)k * DDIM + n];
    __nv_bfloat16 h = __float2bfloat16(val);
    g_Wo_hi[idx] = h;
    g_Wo_lo[idx] = __float2bfloat16(val - __bfloat162float(h));
}

__global__ void split_x_kernel(const float* __restrict__ x) {
    size_t idx = (size_t)blockIdx.x * blockDim.x + threadIdx.x;
    if (idx >= (size_t)BS * DDIM) return;
    float v = x[idx];
    __nv_bfloat16 h = __float2bfloat16(v);
    g_X_hi[idx] = h;
    g_X_lo[idx] = __float2bfloat16(v - __bfloat162float(h));
}

// ---------------------------------------------------------------------------
// HMMA split-bf16 GEMM (R5 config): C[M,N] = (Ah+Al)[M,K] @ (Bh+Bl)^T,
// B stored [N][K]. 128x128 block tile, 8 warps (2m x 4n, warp tile 64x32),
// k-chunk 32, cp.async double buffer. SMEM rows padded to 80B.
// __launch_bounds__(256,2) pins regs <= 128 so 2 CTAs/SM stay resident.
// ---------------------------------------------------------------------------
#define GRS   80                       // smem row stride bytes (64 data + 16)
#define GMATB (128 * GRS)              // 10240 B per matrix plane
#define GBUFB (4 * GMATB)              // 40960 B per buffer
#define GEMM_SMEM (2 * GBUFB)          // 81920 B

__device__ __forceinline__
void hgemm_body(const __nv_bfloat16* __restrict__ Ah,
                const __nv_bfloat16* __restrict__ Al,
                const __nv_bfloat16* __restrict__ Bh,
                const __nv_bfloat16* __restrict__ Bl,
                float* __restrict__ C, int N, int K) {
    extern __shared__ char gsm[];
    const uint32_t sb = smem_to_u32(gsm);
    const int tid = threadIdx.x, lane = tid & 31;
    const int wid = tid >> 5;
    const int wm = wid & 1, wn = wid >> 1;
    const int bm = blockIdx.y * 128, bn = blockIdx.x * 128;

    float acc[4][4][4];
#pragma unroll
    for (int i = 0; i < 4; i++)
#pragma unroll
        for (int j = 0; j < 4; j++)
#pragma unroll
            for (int e = 0; e < 4; e++) acc[i][j][e] = 0.0f;

    auto issue = [&](int k0, int buf) {
#pragma unroll
        for (int i = 0; i < 8; i++) {
            int idx = tid + i * 256;
            int mat = idx >> 9, t = idx & 511, r = t >> 2, q = t & 3;
            const __nv_bfloat16* g; int rb;
            if (mat == 0)      { g = Ah; rb = bm; }
            else if (mat == 1) { g = Al; rb = bm; }
            else if (mat == 2) { g = Bh; rb = bn; }
            else               { g = Bl; rb = bn; }
            uint32_t dst = sb + buf * GBUFB + mat * GMATB + r * GRS + q * 16;
            cp16(dst, g + (size_t)(rb + r) * K + k0 + q * 8);
        }
        CP_COMMIT();
    };

    const int nch = K / 32;
    issue(0, 0);
    for (int j = 0; j < nch; j++) {
        if (j + 1 < nch) { issue((j + 1) * 32, (j + 1) & 1); CP_WAIT1(); }
        else             { CP_WAIT0(); }
        __syncthreads();
        const uint32_t base = sb + (j & 1) * GBUFB;
#pragma unroll
        for (int ks = 0; ks < 2; ks++) {
            uint32_t ah[4][4], al[4][4];
#pragma unroll
            for (int mt = 0; mt < 4; mt++) {
                uint32_t a = base + (wm * 64 + mt * 16 + (lane & 15)) * GRS
                           + ks * 32 + (lane >> 4) * 16;
                ldsm_x4(ah[mt], a);
                ldsm_x4(al[mt], a + GMATB);
            }
            uint32_t bh[4][2], bl[4][2];
#pragma unroll
            for (int p = 0; p < 2; p++) {
                uint32_t r4[4], r4l[4];
                uint32_t a = base + 2 * GMATB
                           + (wn * 32 + p * 16 + (lane & 15)) * GRS
                           + ks * 32 + (lane >> 4) * 16;
                ldsm_x4(r4, a);
                ldsm_x4(r4l, a + GMATB);
                bh[2*p][0] = r4[0];  bh[2*p][1] = r4[2];
                bh[2*p+1][0] = r4[1]; bh[2*p+1][1] = r4[3];
                bl[2*p][0] = r4l[0]; bl[2*p][1] = r4l[2];
                bl[2*p+1][0] = r4l[1]; bl[2*p+1][1] = r4l[3];
            }
#pragma unroll
            for (int mt = 0; mt < 4; mt++)
#pragma unroll
                for (int nt = 0; nt < 4; nt++) {
                    mma16816(acc[mt][nt], ah[mt], bh[nt][0], bh[nt][1]);
                    mma16816(acc[mt][nt], al[mt], bh[nt][0], bh[nt][1]);
                    mma16816(acc[mt][nt], ah[mt], bl[nt][0], bl[nt][1]);
                }
        }
        __syncthreads();
    }

#pragma unroll
    for (int mt = 0; mt < 4; mt++)
#pragma unroll
        for (int nt = 0; nt < 4; nt++) {
            int row = bm + wm * 64 + mt * 16 + (lane >> 2);
            int col = bn + wn * 32 + nt * 8 + ((lane & 3) << 1);
            *(float2*)(C + (size_t)row * N + col) =
                make_float2(acc[mt][nt][0], acc[mt][nt][1]);
            *(float2*)(C + (size_t)(row + 8) * N + col) =
                make_float2(acc[mt][nt][2], acc[mt][nt][3]);
        }
}

__global__ __launch_bounds__(256, 2)
void gemm_proj_hmma() {
    hgemm_body(g_X_hi, g_X_lo, g_Wc_hi, g_Wc_lo, g_proj, NPAD, DDIM);
}
__global__ __launch_bounds__(256, 2)
void gemm_out_hmma(float* __restrict__ out) {
    hgemm_body(g_A_hi, g_A_lo, g_Wo_hi, g_Wo_lo, out, DDIM, DDIM);
}

// ---------------------------------------------------------------------------
// Kernel 3: per-token RoPE + rank contraction; emits q,k,v as bf16 hi/lo
// ---------------------------------------------------------------------------
__global__ __launch_bounds__(128)
void qkv_kernel(const float* __restrict__ cosg, const float* __restrict__ sing) {
    const int t = blockIdx.x;
    const int b = t >> 11;
    const int s = t & 2047;
    const float* __restrict__ row = &g_proj[(size_t)t * NPAD];

    __shared__ float aq[96];
    __shared__ float akv[16];
    __shared__ float bq[QR][HD];
    __shared__ float bk[RR][HD];
    __shared__ float bv[RR][HD];
    __shared__ float cs[64], sn[64];

    const int tid = threadIdx.x;
    if (tid < 64) { cs[tid] = cosg[(size_t)t * 64 + tid]; sn[tid] = sing[(size_t)t * 64 + tid]; }
    if (tid < 96) aq[tid] = row[tid];
    if (tid >= 96 && tid < 112) akv[tid - 96] = row[tid];
    __syncthreads();

    for (int p = tid; p < QR * 64; p += 128) {
        int r = p >> 6, d = p & 63;
        float x1 = row[112 + r * HD + d];
        float x2 = row[112 + r * HD + 64 + d];
        bq[r][d]      = x1 * cs[d] - x2 * sn[d];
        bq[r][64 + d] = x2 * cs[d] + x1 * sn[d];
    }
    {
        int r = tid >> 6, d = tid & 63;
        float x1 = row[880 + r * HD + d];
        float x2 = row[880 + r * HD + 64 + d];
        bk[r][d]      = x1 * cs[d] - x2 * sn[d];
        bk[r][64 + d] = x2 * cs[d] + x1 * sn[d];
    }
    for (int p = tid; p < RR * HD; p += 128) {
        bv[p >> 7][p & 127] = row[1136 + p];
    }
    __syncthreads();

    for (int idx = tid; idx < HEADS * HD; idx += 128) {
        int h = idx >> 7, d = idx & 127;
        float acc = 0.0f;
#pragma unroll
        for (int r = 0; r < QR; r++) acc += aq[h * QR + r] * bq[r][d];
        acc *= (1.0f / QR);
        size_t o = (((size_t)b * HEADS + h) * SDIM + s) * HD + d;
        __nv_bfloat16 hh = __float2bfloat16(acc);
        g_qhi[o] = hh;
        g_qlo[o] = __float2bfloat16(acc - __bfloat162float(hh));
    }
    for (int idx = tid; idx < KVH * HD; idx += 128) {
        int kh = idx >> 7, d = idx & 127;
        float ak0 = akv[kh * RR + 0], ak1 = akv[kh * RR + 1];
        float av0 = akv[8 + kh * RR + 0], av1 = akv[8 + kh * RR + 1];
        size_t o = (((size_t)b * KVH + kh) * SDIM + s) * HD + d;
        float kv = (ak0 * bk[0][d] + ak1 * bk[1][d]) * 0.5f;
        float vv = (av0 * bv[0][d] + av1 * bv[1][d]) * 0.5f;
        __nv_bfloat16 kh16 = __float2bfloat16(kv);
        g_khi[o] = kh16;
        g_klo[o] = __float2bfloat16(kv - __bfloat162float(kh16));
        __nv_bfloat16 vh16 = __float2bfloat16(vv);
        g_vhi[o] = vh16;
        g_vlo[o] = __float2bfloat16(vv - __bfloat162float(vh16));
    }
}

// ---------------------------------------------------------------------------
// Kernel 4: HMMA causal flash attention with logsumexp sink gate.
// Block: 128 q-rows x one (b,h); 8 warps, warp owns 16 q-rows.
// KT=64 key tiles. K/V hi/lo double-buffered via cp.async.
// qt is REVERSED vs blockIdx.x so the longest (most tiles) CTAs launch first.
// ---------------------------------------------------------------------------
#define FRS 272                         // smem row stride bytes (256 + 16)
#define FQ_OFF  0                       // Q hi (128 rows)
#define FQL_OFF 34816                   // Q lo
#define KV0_OFF 69632                   // KV buffers start
#define KVPLANE 17408                   // 64 rows * 272
#define KVBUF   (4 * KVPLANE)           // Khi,Klo,Vhi,Vlo = 69632
#define FLASH_SMEM (KV0_OFF + 2 * KVBUF)   // 208896

__global__ __launch_bounds__(256, 1)
void flash_hmma(const float* __restrict__ sinks) {
    extern __shared__ char fsm[];
    const uint32_t sb = smem_to_u32(fsm);
    const int tid = threadIdx.x, lane = tid & 31, wid = tid >> 5;
    const int qt = (int)gridDim.x - 1 - (int)blockIdx.x;   // longest first
    const int h = blockIdx.y, b = blockIdx.z;
    const int qbase = qt * 128;
    const int wrow = wid * 16;

    const size_t kvbase = ((size_t)(b * KVH + (h >> 2))) * SDIM * HD;

    // prefetch lambda: K/V hi/lo tile jj into buffer buf
    auto kv_issue = [&](int jj, int buf) {
        const __nv_bfloat16* kh = g_khi + kvbase + (size_t)jj * 64 * HD;
        const __nv_bfloat16* kl = g_klo + kvbase + (size_t)jj * 64 * HD;
        const __nv_bfloat16* vh = g_vhi + kvbase + (size_t)jj * 64 * HD;
        const __nv_bfloat16* vl = g_vlo + kvbase + (size_t)jj * 64 * HD;
        const uint32_t kb = sb + KV0_OFF + buf * KVBUF;
        for (int u = tid; u < 1024; u += 256) {
            int r = u >> 4, c = u & 15;
            uint32_t o = r * FRS + c * 16;
            size_t gi = (size_t)r * HD + c * 8;
            cp16(kb + o,               kh + gi);
            cp16(kb + KVPLANE + o,     kl + gi);
            cp16(kb + 2 * KVPLANE + o, vh + gi);
            cp16(kb + 3 * KVPLANE + o, vl + gi);
        }
        CP_COMMIT();
    };

    // load Q tile (hi/lo planes) with plain loads
    {
        const __nv_bfloat16* qh = g_qhi + (((size_t)(b * HEADS + h)) * SDIM + qbase) * HD;
        const __nv_bfloat16* ql = g_qlo + (((size_t)(b * HEADS + h)) * SDIM + qbase) * HD;
        for (int u = tid; u < 2048; u += 256) {
            int r = u >> 4, c = u & 15;
            *(uint4*)(fsm + FQ_OFF  + r * FRS + c * 16) = *(const uint4*)(qh + r * HD + c * 8);
            *(uint4*)(fsm + FQL_OFF + r * FRS + c * 16) = *(const uint4*)(ql + r * HD + c * 8);
        }
    }

    float m0 = -1e30f, m1 = -1e30f, l0 = 0.0f, l1 = 0.0f;
    float acc[16][4];
#pragma unroll
    for (int i = 0; i < 16; i++)
#pragma unroll
        for (int e = 0; e < 4; e++) acc[i][e] = 0.0f;

    const int nkt = 2 * qt + 2;
    const float SC = 0.08838834764831843f;   // HD^-0.5

    kv_issue(0, 0);
    for (int j = 0; j < nkt; j++) {
        if (j + 1 < nkt) { kv_issue(j + 1, (j + 1) & 1); CP_WAIT1(); }
        else             { CP_WAIT0(); }
        __syncthreads();
        const uint32_t kvb = sb + KV0_OFF + (j & 1) * KVBUF;

        // ---- S = Q K^T (3-pass split bf16) ----
        float s[8][4];
#pragma unroll
        for (int nt = 0; nt < 8; nt++)
#pragma unroll
            for (int e = 0; e < 4; e++) s[nt][e] = 0.0f;

#pragma unroll
        for (int ks = 0; ks < 8; ks++) {
            uint32_t ah[4], alo[4];
            uint32_t aaddr = sb + FQ_OFF + (wrow + (lane & 15)) * FRS
                           + ks * 32 + (lane >> 4) * 16;
            ldsm_x4(ah, aaddr);
            ldsm_x4(alo, aaddr + (FQL_OFF - FQ_OFF));
#pragma unroll
            for (int p = 0; p < 4; p++) {
                uint32_t kb4[4], klr[4];
                uint32_t baddr = kvb + (p * 16 + (lane & 15)) * FRS
                               + ks * 32 + (lane >> 4) * 16;
                ldsm_x4(kb4, baddr);
                ldsm_x4(klr, baddr + KVPLANE);
                mma16816(s[2*p],   ah,  kb4[0], kb4[2]);
                mma16816(s[2*p],   alo, kb4[0], kb4[2]);
                mma16816(s[2*p],   ah,  klr[0], klr[2]);
                mma16816(s[2*p+1], ah,  kb4[1], kb4[3]);
                mma16816(s[2*p+1], alo, kb4[1], kb4[3]);
                mma16816(s[2*p+1], ah,  klr[1], klr[3]);
            }
        }

        // ---- scale + causal mask ----
        const int r0 = qbase + wrow + (lane >> 2);
        const bool tail = (j >= 2 * qt);
#pragma unroll
        for (int nt = 0; nt < 8; nt++) {
            int kc = j * 64 + nt * 8 + ((lane & 3) << 1);
            s[nt][0] *= SC; s[nt][1] *= SC; s[nt][2] *= SC; s[nt][3] *= SC;
            if (tail) {
                if (kc     > r0)     s[nt][0] = -1e30f;
                if (kc + 1 > r0)     s[nt][1] = -1e30f;
                if (kc     > r0 + 8) s[nt][2] = -1e30f;
                if (kc + 1 > r0 + 8) s[nt][3] = -1e30f;
            }
        }

        // ---- online softmax (rows r0, r0+8), quad reductions ----
        float mx0 = -1e30f, mx1 = -1e30f;
#pragma unroll
        for (int nt = 0; nt < 8; nt++) {
            mx0 = fmaxf(mx0, fmaxf(s[nt][0], s[nt][1]));
            mx1 = fmaxf(mx1, fmaxf(s[nt][2], s[nt][3]));
        }
        mx0 = fmaxf(mx0, __shfl_xor_sync(0xffffffffu, mx0, 1));
        mx0 = fmaxf(mx0, __shfl_xor_sync(0xffffffffu, mx0, 2));
        mx1 = fmaxf(mx1, __shfl_xor_sync(0xffffffffu, mx1, 1));
        mx1 = fmaxf(mx1, __shfl_xor_sync(0xffffffffu, mx1, 2));
        float mn0 = fmaxf(m0, mx0), mn1 = fmaxf(m1, mx1);
        float a0 = __expf(m0 - mn0), a1 = __expf(m1 - mn1);
        float sum0 = 0.0f, sum1 = 0.0f;
#pragma unroll
        for (int nt = 0; nt < 8; nt++) {
            s[nt][0] = __expf(s[nt][0] - mn0); sum0 += s[nt][0];
            s[nt][1] = __expf(s[nt][1] - mn0); sum0 += s[nt][1];
            s[nt][2] = __expf(s[nt][2] - mn1); sum1 += s[nt][2];
            s[nt][3] = __expf(s[nt][3] - mn1); sum1 += s[nt][3];
        }
        sum0 += __shfl_xor_sync(0xffffffffu, sum0, 1);
        sum0 += __shfl_xor_sync(0xffffffffu, sum0, 2);
        sum1 += __shfl_xor_sync(0xffffffffu, sum1, 1);
        sum1 += __shfl_xor_sync(0xffffffffu, sum1, 2);
        l0 = l0 * a0 + sum0; l1 = l1 * a1 + sum1;
        m0 = mn0; m1 = mn1;
#pragma unroll
        for (int dt = 0; dt < 16; dt++) {
            acc[dt][0] *= a0; acc[dt][1] *= a0;
            acc[dt][2] *= a1; acc[dt][3] *= a1;
        }

        // ---- PV: P split to bf16 hi/lo, V from SMEM via ldmatrix.trans ----
#pragma unroll
        for (int kt = 0; kt < 4; kt++) {
            uint32_t ph[4], pl[4];
            split2(s[2*kt][0],   s[2*kt][1],   ph[0], pl[0]);
            split2(s[2*kt][2],   s[2*kt][3],   ph[1], pl[1]);
            split2(s[2*kt+1][0], s[2*kt+1][1], ph[2], pl[2]);
            split2(s[2*kt+1][2], s[2*kt+1][3], ph[3], pl[3]);
#pragma unroll
            for (int dp = 0; dp < 8; dp++) {
                uint32_t vh[4], vl[4];
                uint32_t vaddr = kvb + 2 * KVPLANE + (kt * 16 + (lane & 15)) * FRS
                               + dp * 32 + (lane >> 4) * 16;
                ldsm_x4_t(vh, vaddr);
                ldsm_x4_t(vl, vaddr + KVPLANE);
                mma16816(acc[2*dp],   ph, vh[0], vh[1]);
                mma16816(acc[2*dp],   pl, vh[0], vh[1]);
                mma16816(acc[2*dp],   ph, vl[0], vl[1]);
                mma16816(acc[2*dp+1], ph, vh[2], vh[3]);
                mma16816(acc[2*dp+1], pl, vh[2], vh[3]);
                mma16816(acc[2*dp+1], ph, vl[2], vl[3]);
            }
        }
        __syncthreads();   // all warps done with this buffer before reuse
    }

    // ---- epilogue: sink gate, normalize, write bf16 hi/lo attention out ----
    const float sink = sinks[h];
    float logz0 = m0 + logf(l0);
    float logz1 = m1 + logf(l1);
    float sc0 = (1.0f / (1.0f + __expf(sink - logz0))) / l0;
    float sc1 = (1.0f / (1.0f + __expf(sink - logz1))) / l1;
    const int tok0 = b * SDIM + qbase + wrow + (lane >> 2);
    const int tok1 = tok0 + 8;
#pragma unroll
    for (int dt = 0; dt < 16; dt++) {
        int col = h * HD + dt * 8 + ((lane & 3) << 1);
        uint32_t hi, lo;
        split2(acc[dt][0] * sc0, acc[dt][1] * sc0, hi, lo);
        *(uint32_t*)(g_A_hi + (size_t)tok0 * DDIM + col) = hi;
        *(uint32_t*)(g_A_lo + (size_t)tok0 * DDIM + col) = lo;
        split2(acc[dt][2] * sc1, acc[dt][3] * sc1, hi, lo);
        *(uint32_t*)(g_A_hi + (size_t)tok1 * DDIM + col) = hi;
        *(uint32_t*)(g_A_lo + (size_t)tok1 * DDIM + col) = lo;
    }
}

// ---------------------------------------------------------------------------
// launch
// ---------------------------------------------------------------------------
extern "C" void kernel_launch(void* const* d_in, const int* in_sizes, int n_in,
                              void* d_out, int out_size) {
    const float* hs    = (const float*)d_in[0];
    const float* cosg  = (const float*)d_in[1];
    const float* sing  = (const float*)d_in[2];
    // d_in[3] = attention_mask (pure causal; reproduced analytically)
    const float* waq   = (const float*)d_in[4];
    const float* wak   = (const float*)d_in[5];
    const float* wav   = (const float*)d_in[6];
    const float* wbq   = (const float*)d_in[7];
    const float* wbk   = (const float*)d_in[8];
    const float* wbv   = (const float*)d_in[9];
    const float* wo    = (const float*)d_in[10];
    const float* sinks = (const float*)d_in[11];
    float* out = (float*)d_out;

    cudaFuncSetAttribute(gemm_proj_hmma,
                         cudaFuncAttributeMaxDynamicSharedMemorySize, GEMM_SMEM);
    cudaFuncSetAttribute(gemm_out_hmma,
                         cudaFuncAttributeMaxDynamicSharedMemorySize, GEMM_SMEM);
    cudaFuncSetAttribute(flash_hmma,
                         cudaFuncAttributeMaxDynamicSharedMemorySize, FLASH_SMEM);

    // 1. pack + split weights and activations
    {
        size_t n = (size_t)NPAD * DDIM;
        pack_w_kernel<<<(unsigned)((n + 255) / 256), 256>>>(waq, wak, wav, wbq, wbk, wbv);
    }
    {
        size_t n = (size_t)DDIM * DDIM;
        pack_wo_kernel<<<(unsigned)((n + 255) / 256), 256>>>(wo);
    }
    {
        size_t n = (size_t)BS * DDIM;
        split_x_kernel<<<(unsigned)((n + 255) / 256), 256>>>(hs);
    }
    // 2. fused projection GEMM (HMMA): (4096 x 2048) @ (2048 x 1408)
    gemm_proj_hmma<<<dim3(NPAD / 128, BS / 128), 256, GEMM_SMEM>>>();
    // 3. rope + q/k/v assembly (emits bf16 hi/lo)
    qkv_kernel<<<BS, 128>>>(cosg, sing);
    // 4. HMMA flash attention with sink gate (K/V double-buffered, longest-first)
    flash_hmma<<<dim3(SDIM / 128, HEADS, BDIM), 256, FLASH_SMEM>>>(sinks);
    // 5. output GEMM (HMMA): (4096 x 2048) @ (2048 x 2048) -> d_out
    gemm_out_hmma<<<dim3(DDIM / 128, BS / 128), 256, GEMM_SMEM>>>(out);
}